// round 3
// baseline (speedup 1.0000x reference)
#include <cuda_runtime.h>
#include <math.h>

struct RectCtx {
    float Ax, Ay, Bx, By;
    float ABx, ABy, BCx, BCy;
    float ABABe, BCBCe;   // ABAB + eps, BCBC + eps (precomputed)
};

#define EPS_IN 0.01f
#define NTHREADS 128

__device__ __forceinline__ RectCtx make_ctx(const float2* r) {
    RectCtx c;
    c.Ax = r[0].x; c.Ay = r[0].y;
    c.Bx = r[1].x; c.By = r[1].y;
    c.ABx = r[1].x - r[0].x; c.ABy = r[1].y - r[0].y;
    c.BCx = r[2].x - r[1].x; c.BCy = r[2].y - r[1].y;
    c.ABABe = c.ABx * c.ABx + c.ABy * c.ABy + EPS_IN;
    c.BCBCe = c.BCx * c.BCx + c.BCy * c.BCy + EPS_IN;
    return c;
}

// Reference is_point_in_rect with eps=0.01. NaN/Inf coords -> false (IEEE).
__device__ __forceinline__ bool in_rect(float px_, float py_, const RectCtx& c) {
    float ABAM = c.ABx * (px_ - c.Ax) + c.ABy * (py_ - c.Ay);
    float BCBM = c.BCx * (px_ - c.Bx) + c.BCy * (py_ - c.By);
    return (ABAM >= -EPS_IN) && (ABAM <= c.ABABe) &&
           (BCBM >= -EPS_IN) && (BCBM <= c.BCBCe);
}

// Diamond pseudo-angle: strictly monotone in atan2(u, v), range [-2, 2].
__device__ __forceinline__ float pseudo_ang(float u, float v) {
    float t = fabsf(u) + fabsf(v);
    float r = (t > 0.0f) ? __fdividef(v, t) : 1.0f;
    return copysignf(1.0f - r, u);
}

__global__ void __launch_bounds__(NTHREADS, 7)
obb_iou_kernel(const float* __restrict__ b1,
               const float* __restrict__ b2,
               float* __restrict__ out, int n) {
    __shared__ float2 sc[24][NTHREADS];   // 24 KB: per-thread 24-point scratch
    int tid = threadIdx.x;
    int i = blockIdx.x * NTHREADS + tid;
    if (i >= n) return;

    // ---- load rects (two float4 loads each) ----
    float2 r1[4], r2[4];
    {
        const float4* p1 = reinterpret_cast<const float4*>(b1 + (size_t)i * 8);
        const float4* p2 = reinterpret_cast<const float4*>(b2 + (size_t)i * 8);
        float4 a0 = p1[0], a1v = p1[1];
        float4 c0 = p2[0], c1v = p2[1];
        r1[0] = make_float2(a0.x, a0.y);  r1[1] = make_float2(a0.z, a0.w);
        r1[2] = make_float2(a1v.x, a1v.y); r1[3] = make_float2(a1v.z, a1v.w);
        r2[0] = make_float2(c0.x, c0.y);  r2[1] = make_float2(c0.z, c0.w);
        r2[2] = make_float2(c1v.x, c1v.y); r2[3] = make_float2(c1v.z, c1v.w);
    }

    // ---- rectangle areas early (frees dependence on r later) ----
    float a1 = fabsf(r1[0].x * (r1[1].y - r1[2].y) +
                     r1[1].x * (r1[2].y - r1[0].y) +
                     r1[2].x * (r1[0].y - r1[1].y));
    float a2 = fabsf(r2[0].x * (r2[1].y - r2[2].y) +
                     r2[1].x * (r2[2].y - r2[0].y) +
                     r2[2].x * (r2[0].y - r2[1].y));

    // ---- 16 edge-edge line intersections (forms identical to reference) ----
    float px[24], py[24];
    #pragma unroll
    for (int e1 = 0; e1 < 4; e1++) {
        float2 P1 = r1[e1], P2 = r1[(e1 + 1) & 3];
        float a    = P1.x * P2.y - P1.y * P2.x;
        float dx12 = P1.x - P2.x, dy12 = P1.y - P2.y;
        #pragma unroll
        for (int e2 = 0; e2 < 4; e2++) {
            float2 P3 = r2[e2], P4 = r2[(e2 + 1) & 3];
            float b    = P3.x * P4.y - P3.y * P4.x;
            float dx34 = P3.x - P4.x, dy34 = P3.y - P4.y;
            float den = dx12 * dy34 - dy12 * dx34;
            if (fabsf(den) < 1e-12f) den = 1e-12f;      // reference clamp
            float rden = __fdividef(1.0f, den);
            int k = e1 * 4 + e2;
            px[k] = (a * dx34 - dx12 * b) * rden;
            py[k] = (a * dy34 - dy12 * b) * rden;
            sc[k][tid] = make_float2(px[k], py[k]);
        }
    }
    #pragma unroll
    for (int k = 0; k < 4; k++) {
        px[16 + k] = r1[k].x; py[16 + k] = r1[k].y;
        sc[16 + k][tid] = make_float2(px[16 + k], py[16 + k]);
        px[20 + k] = r2[k].x; py[20 + k] = r2[k].y;
        sc[20 + k][tid] = make_float2(px[20 + k], py[20 + k]);
    }

    // ---- membership mask (eps = 0.01) ----
    RectCtx c1 = make_ctx(r1);
    RectCtx c2 = make_ctx(r2);
    unsigned mask = 0u;
    #pragma unroll
    for (int k = 0; k < 16; k++)
        if (in_rect(px[k], py[k], c1) && in_rect(px[k], py[k], c2))
            mask |= 1u << k;
    #pragma unroll
    for (int k = 0; k < 4; k++)
        if (in_rect(px[16 + k], py[16 + k], c2)) mask |= 1u << (16 + k);
    #pragma unroll
    for (int k = 0; k < 4; k++)
        if (in_rect(px[20 + k], py[20 + k], c1)) mask |= 1u << (20 + k);

    // ---- duplicates: keep[i] = !any_{j<i}( L1(p_i,p_j) < 0.01 ) ----
    // Same-rect vertex pairs skipped: corner L1 distance >= 2 >> 0.01.
    unsigned keep = 1u;
    #pragma unroll
    for (int a_ = 1; a_ < 24; a_++) {
        float ax = px[a_], ay = py[a_];
        bool dup = false;
        // columns: all j < a_, minus same-rect vertex pairs
        int jmax = (a_ <= 16) ? a_ : ((a_ <= 20) ? 16 : 20);
        #pragma unroll
        for (int b_ = 0; b_ < 23; b_++) {
            if (b_ < jmax) {
                float d = fabsf(ax - px[b_]) + fabsf(ay - py[b_]);
                dup = dup || (d < 0.01f);   // NaN -> false (JAX semantics)
            }
        }
        if (!dup) keep |= 1u << a_;
    }

    unsigned mk = mask & keep;
    int cnt = __popc(mk);

    if (cnt < 3) {            // reference yields zero intersection area
        out[i] = 0.0f;
        return;
    }
    if (cnt > 8) cnt = 8;

    // ---- gather first-8 set bits from smem scratch (stable top_k order) ----
    float kx[8], ky[8];
    float sx = 0.0f, sy = 0.0f;
    unsigned m = mk;
    #pragma unroll
    for (int t = 0; t < 8; t++) {
        if (t < cnt) {
            int idx = __ffs(m) - 1;
            m &= m - 1u;
            float2 p = sc[idx][tid];
            kx[t] = p.x; ky[t] = p.y;
            sx += p.x;   sy += p.y;
        }
    }
    #pragma unroll
    for (int t = 3; t < 8; t++) {        // cnt >= 3 guaranteed
        if (t >= cnt) { kx[t] = kx[0]; ky[t] = ky[0]; }
    }

    // ---- centroid over valid points (matches sum(pp*m)/(sum(m)+1e-6)) ----
    float smf = (float)cnt;
    float cxx = __fdividef(sx, smf + 1e-6f);
    float cyy = __fdividef(sy, smf + 1e-6f);

    // ---- center + pseudo-angle keys, wrapped to start at slot 0 ----
    float w[8];
    #pragma unroll
    for (int t = 0; t < 8; t++) {
        kx[t] -= cxx; ky[t] -= cyy;
        w[t] = pseudo_ang(kx[t], ky[t]);
    }
    float p0 = w[0];
    #pragma unroll
    for (int t = 0; t < 8; t++) {
        float d = w[t] - p0;
        w[t] = (d < 0.0f) ? d + 4.0f : d;   // pseudo-angle period = 4
    }

    // ---- 8-element Batcher sorting network on (w, kx, ky) ----
    #define CE(A, B) { \
        float wa = w[A], wb = w[B]; bool p_ = wa > wb; \
        w[A] = fminf(wa, wb); w[B] = fmaxf(wa, wb); \
        float tx = kx[A]; kx[A] = p_ ? kx[B] : tx; kx[B] = p_ ? tx : kx[B]; \
        float ty = ky[A]; ky[A] = p_ ? ky[B] : ty; ky[B] = p_ ? ty : ky[B]; }
    CE(0,1) CE(2,3) CE(4,5) CE(6,7)
    CE(0,2) CE(1,3) CE(4,6) CE(5,7)
    CE(1,2) CE(5,6) CE(0,4) CE(3,7)
    CE(1,5) CE(2,6)
    CE(1,4) CE(3,6)
    CE(2,4) CE(3,5)
    CE(3,4)
    #undef CE

    // ---- fan triangulation from sorted vertex 0 ----
    float s0x = kx[0], s0y = ky[0];
    float inter = 0.0f;
    #pragma unroll
    for (int t = 1; t <= 6; t++) {
        float axp = kx[t],     ayp = ky[t];
        float bxp = kx[t + 1], byp = ky[t + 1];
        inter += 0.5f * fabsf(s0x * (ayp - byp) + axp * (byp - s0y) + bxp * (s0y - ayp));
    }

    float uni = a1 + a2 - inter;
    out[i] = __fdividef(inter, uni);
}

extern "C" void kernel_launch(void* const* d_in, const int* in_sizes, int n_in,
                              void* d_out, int out_size) {
    const float* b1 = (const float*)d_in[0];
    const float* b2 = (const float*)d_in[1];
    float* out = (float*)d_out;
    int n = in_sizes[0] / 8;   // [N,4,2] floats
    int blocks = (n + NTHREADS - 1) / NTHREADS;
    obb_iou_kernel<<<blocks, NTHREADS>>>(b1, b2, out, n);
}

// round 5
// speedup vs baseline: 1.0077x; 1.0077x over previous
#include <cuda_runtime.h>
#include <math.h>

#define EPS_IN 0.01f
#define NTHREADS 128
#define NBLOCKS  592   // 148 SMs x 4 CTAs/SM -> single wave for regs <= 128

// Diamond pseudo-angle: strictly monotone in atan2(u, v), range [-2, 2].
__device__ __forceinline__ float pseudo_ang(float u, float v) {
    float t = fabsf(u) + fabsf(v);
    float r = (t > 0.0f) ? __fdividef(v, t) : 1.0f;
    return copysignf(1.0f - r, u);
}

__global__ void __launch_bounds__(NTHREADS)
obb_iou_kernel(const float* __restrict__ b1,
               const float* __restrict__ b2,
               float* __restrict__ out, int n) {
    const int stride = NBLOCKS * NTHREADS;
    for (int i = blockIdx.x * NTHREADS + threadIdx.x; i < n; i += stride) {

        // ---- load rects (two float4 loads each) ----
        float2 r1[4], r2[4];
        {
            const float4* p1 = reinterpret_cast<const float4*>(b1 + (size_t)i * 8);
            const float4* p2 = reinterpret_cast<const float4*>(b2 + (size_t)i * 8);
            float4 a0 = p1[0], a1v = p1[1];
            float4 c0 = p2[0], c1v = p2[1];
            r1[0] = make_float2(a0.x, a0.y);   r1[1] = make_float2(a0.z, a0.w);
            r1[2] = make_float2(a1v.x, a1v.y); r1[3] = make_float2(a1v.z, a1v.w);
            r2[0] = make_float2(c0.x, c0.y);   r2[1] = make_float2(c0.z, c0.w);
            r2[2] = make_float2(c1v.x, c1v.y); r2[3] = make_float2(c1v.z, c1v.w);
        }

        // ---- rect axis data (shared by all in-rect tests) ----
        // rect1: AB axis from A=r1[0], BC axis from B=r1[1]
        float AB1x = r1[1].x - r1[0].x, AB1y = r1[1].y - r1[0].y;
        float BC1x = r1[2].x - r1[1].x, BC1y = r1[2].y - r1[1].y;
        float AB1e = AB1x * AB1x + AB1y * AB1y + EPS_IN;
        float BC1e = BC1x * BC1x + BC1y * BC1y + EPS_IN;
        float AB2x = r2[1].x - r2[0].x, AB2y = r2[1].y - r2[0].y;
        float BC2x = r2[2].x - r2[1].x, BC2y = r2[2].y - r2[1].y;
        float AB2e = AB2x * AB2x + AB2y * AB2y + EPS_IN;
        float BC2e = BC2x * BC2x + BC2y * BC2y + EPS_IN;

        // ---- hoisted per-e2 line quantities ----
        float bb[4], d34x[4], d34y[4];
        #pragma unroll
        for (int e2 = 0; e2 < 4; e2++) {
            float2 P3 = r2[e2], P4 = r2[(e2 + 1) & 3];
            bb[e2]   = P3.x * P4.y - P3.y * P4.x;
            d34x[e2] = P3.x - P4.x;
            d34y[e2] = P3.y - P4.y;
        }

        // ---- 16 intersections + reduced in-rect tests (1 axis per rect) ----
        float px[24], py[24];
        unsigned mask = 0u;
        #pragma unroll
        for (int e1 = 0; e1 < 4; e1++) {
            float2 P1 = r1[e1], P2 = r1[(e1 + 1) & 3];
            float a    = P1.x * P2.y - P1.y * P2.x;
            float dx12 = P1.x - P2.x, dy12 = P1.y - P2.y;
            #pragma unroll
            for (int e2 = 0; e2 < 4; e2++) {
                float den = dx12 * d34y[e2] - dy12 * d34x[e2];
                if (fabsf(den) < 1e-12f) den = 1e-12f;      // reference clamp
                float rden = __fdividef(1.0f, den);
                float Px = (a * d34x[e2] - dx12 * bb[e2]) * rden;
                float Py = (a * d34y[e2] - dy12 * bb[e2]) * rden;
                int k = e1 * 4 + e2;
                px[k] = Px; py[k] = Py;
                // along-edge test vs rect1: e1 even -> AB1 axis, odd -> BC1 axis
                float t1 = (e1 & 1)
                    ? BC1x * (Px - r1[1].x) + BC1y * (Py - r1[1].y)
                    : AB1x * (Px - r1[0].x) + AB1y * (Py - r1[0].y);
                float h1 = (e1 & 1) ? BC1e : AB1e;
                // along-edge test vs rect2: e2 even -> AB2 axis, odd -> BC2 axis
                float t2 = (e2 & 1)
                    ? BC2x * (Px - r2[1].x) + BC2y * (Py - r2[1].y)
                    : AB2x * (Px - r2[0].x) + AB2y * (Py - r2[0].y);
                float h2 = (e2 & 1) ? BC2e : AB2e;
                if (t1 >= -EPS_IN && t1 <= h1 && t2 >= -EPS_IN && t2 <= h2)
                    mask |= 1u << k;
            }
        }
        #pragma unroll
        for (int k = 0; k < 4; k++) { px[16 + k] = r1[k].x; py[16 + k] = r1[k].y; }
        #pragma unroll
        for (int k = 0; k < 4; k++) { px[20 + k] = r2[k].x; py[20 + k] = r2[k].y; }

        // ---- vertex-in-other-rect tests (full two-axis tests) ----
        #pragma unroll
        for (int k = 0; k < 4; k++) {
            float Px = r1[k].x, Py = r1[k].y;
            float u = AB2x * (Px - r2[0].x) + AB2y * (Py - r2[0].y);
            float v = BC2x * (Px - r2[1].x) + BC2y * (Py - r2[1].y);
            if (u >= -EPS_IN && u <= AB2e && v >= -EPS_IN && v <= BC2e)
                mask |= 1u << (16 + k);
        }
        #pragma unroll
        for (int k = 0; k < 4; k++) {
            float Px = r2[k].x, Py = r2[k].y;
            float u = AB1x * (Px - r1[0].x) + AB1y * (Py - r1[0].y);
            float v = BC1x * (Px - r1[1].x) + BC1y * (Py - r1[1].y);
            if (u >= -EPS_IN && u <= BC1e * 0.0f + AB1e && v >= -EPS_IN && v <= BC1e)
                mask |= 1u << (20 + k);
        }

        // ---- duplicates: keep[a] = !any_{j<a}( L1 < 0.01 ), same-rect vertex
        //      pairs skipped structurally (corner distance >= 2 >> 0.01) ----
        unsigned keep = 1u;
        #pragma unroll
        for (int a_ = 1; a_ < 16; a_++) {
            float ax = px[a_], ay = py[a_];
            bool dup = false;
            #pragma unroll
            for (int j = 0; j < a_; j++)
                dup = dup || (fabsf(ax - px[j]) + fabsf(ay - py[j]) < 0.01f);
            if (!dup) keep |= 1u << a_;
        }
        #pragma unroll
        for (int a_ = 16; a_ < 20; a_++) {          // r1 vertices: vs 16 inters only
            float ax = px[a_], ay = py[a_];
            bool dup = false;
            #pragma unroll
            for (int j = 0; j < 16; j++)
                dup = dup || (fabsf(ax - px[j]) + fabsf(ay - py[j]) < 0.01f);
            if (!dup) keep |= 1u << a_;
        }
        #pragma unroll
        for (int a_ = 20; a_ < 24; a_++) {          // r2 vertices: vs inters + r1 verts
            float ax = px[a_], ay = py[a_];
            bool dup = false;
            #pragma unroll
            for (int j = 0; j < 20; j++)
                dup = dup || (fabsf(ax - px[j]) + fabsf(ay - py[j]) < 0.01f);
            if (!dup) keep |= 1u << a_;
        }

        unsigned mk = mask & keep;
        int cnt = __popc(mk);

        if (cnt < 3) {          // reference provably yields zero intersection
            out[i] = 0.0f;
            continue;
        }
        if (cnt > 8) cnt = 8;

        // ---- stable top_k(8): first masked indices ascending ----
        float kx[8], ky[8];
        float sx = 0.0f, sy = 0.0f;
        {
            int c = 0;
            #pragma unroll
            for (int k = 0; k < 24; k++) {
                if (((mk >> k) & 1u) && c < 8) {
                    kx[c] = px[k]; ky[c] = py[k];
                    sx += px[k];   sy += py[k];
                    c++;
                }
            }
        }
        #pragma unroll
        for (int t = 3; t < 8; t++) {     // cnt >= 3 guaranteed
            if (t >= cnt) { kx[t] = kx[0]; ky[t] = ky[0]; }
        }

        // ---- centroid over valid points (matches sum(pp*m)/(sum(m)+1e-6)) ----
        float smf = (float)cnt;
        float cxx = __fdividef(sx, smf + 1e-6f);
        float cyy = __fdividef(sy, smf + 1e-6f);

        // ---- center + pseudo-angle keys, wrapped to start at slot 0 ----
        float w[8];
        #pragma unroll
        for (int t = 0; t < 8; t++) {
            kx[t] -= cxx; ky[t] -= cyy;
            w[t] = pseudo_ang(kx[t], ky[t]);
        }
        float p0 = w[0];
        #pragma unroll
        for (int t = 0; t < 8; t++) {
            float d = w[t] - p0;
            w[t] = (d < 0.0f) ? d + 4.0f : d;   // pseudo-angle period = 4
        }

        // ---- 8-element Batcher sorting network on (w, kx, ky) ----
        #define CE(A, B) { \
            float wa = w[A], wb = w[B]; bool p_ = wa > wb; \
            w[A] = fminf(wa, wb); w[B] = fmaxf(wa, wb); \
            float tx = kx[A]; kx[A] = p_ ? kx[B] : tx; kx[B] = p_ ? tx : kx[B]; \
            float ty = ky[A]; ky[A] = p_ ? ky[B] : ty; ky[B] = p_ ? ty : ky[B]; }
        CE(0,1) CE(2,3) CE(4,5) CE(6,7)
        CE(0,2) CE(1,3) CE(4,6) CE(5,7)
        CE(1,2) CE(5,6) CE(0,4) CE(3,7)
        CE(1,5) CE(2,6)
        CE(1,4) CE(3,6)
        CE(2,4) CE(3,5)
        CE(3,4)
        #undef CE

        // ---- fan triangulation from sorted vertex 0 ----
        float s0x = kx[0], s0y = ky[0];
        float inter = 0.0f;
        #pragma unroll
        for (int t = 1; t <= 6; t++) {
            float axp = kx[t],     ayp = ky[t];
            float bxp = kx[t + 1], byp = ky[t + 1];
            inter += 0.5f * fabsf(s0x * (ayp - byp) + axp * (byp - s0y) + bxp * (s0y - ayp));
        }

        // ---- rectangle areas (reference formula) ----
        float a1 = fabsf(r1[0].x * (r1[1].y - r1[2].y) +
                         r1[1].x * (r1[2].y - r1[0].y) +
                         r1[2].x * (r1[0].y - r1[1].y));
        float a2 = fabsf(r2[0].x * (r2[1].y - r2[2].y) +
                         r2[1].x * (r2[2].y - r2[0].y) +
                         r2[2].x * (r2[0].y - r2[1].y));

        float uni = a1 + a2 - inter;
        out[i] = __fdividef(inter, uni);
    }
}

extern "C" void kernel_launch(void* const* d_in, const int* in_sizes, int n_in,
                              void* d_out, int out_size) {
    const float* b1 = (const float*)d_in[0];
    const float* b2 = (const float*)d_in[1];
    float* out = (float*)d_out;
    int n = in_sizes[0] / 8;   // [N,4,2] floats
    int blocks = (n + NTHREADS - 1) / NTHREADS;
    if (blocks > NBLOCKS) blocks = NBLOCKS;
    obb_iou_kernel<<<blocks, NTHREADS>>>(b1, b2, out, n);
}